// round 2
// baseline (speedup 1.0000x reference)
#include <cuda_runtime.h>

// NonLocalBlock: B=8, C=512, H=W=64 -> N=4096, CR=128
//   proj  = w_in[384,512] @ x[b,512,4096]        -> Q,K,G  [b,4096,128] (token-major)
//   attn  = flash-style softmax(Q K^T) G         -> Y      [b,4096,128]
//   out   = x + w_out[512,128] @ Y^T             -> [b,512,4096]

#define BATCH 8
#define CIN   512
#define NTOK  4096
#define CRD   128

// Scratch (allocation-free rule: static __device__ arrays). 16.8 MB each.
__device__ float g_q[(size_t)BATCH * NTOK * CRD];
__device__ float g_k[(size_t)BATCH * NTOK * CRD];
__device__ float g_g[(size_t)BATCH * NTOK * CRD];
__device__ float g_y[(size_t)BATCH * NTOK * CRD];

// ---------------------------------------------------------------------------
// Kernel 1: projection GEMM.  P[b,n,j] = sum_c w_in[j,c] * x[b,c,n]
// Block tile: 64 tokens x 64 out-features, K-tile 32.  grid (64, 6, 8).
// ---------------------------------------------------------------------------
__global__ __launch_bounds__(256) void proj_kernel(const float* __restrict__ x,
                                                   const float* __restrict__ w_in) {
    __shared__ float Xs[32][64];   // [k][n]
    __shared__ float Ws[32][64];   // [k][j]
    const int n0 = blockIdx.x * 64;
    const int j0 = blockIdx.y * 64;
    const int b  = blockIdx.z;
    const int tid = threadIdx.x;
    const int tx = tid & 15, ty = tid >> 4;

    const float* xb = x + (size_t)b * CIN * NTOK + n0;

    float acc[4][4];
#pragma unroll
    for (int u = 0; u < 4; u++)
#pragma unroll
        for (int v = 0; v < 4; v++) acc[u][v] = 0.f;

    for (int c0 = 0; c0 < CIN; c0 += 32) {
        // Xs[k][n] = x[b][c0+k][n0+n]  (rows contiguous in n -> coalesced)
        for (int i = tid; i < 512; i += 256) {
            int k = i >> 4, f = (i & 15) << 2;
            *(float4*)&Xs[k][f] =
                *(const float4*)(xb + (size_t)(c0 + k) * NTOK + f);
        }
        // Ws[k][j] = w_in[j0+j][c0+k]  (read float4 along c, transpose into smem)
        for (int i = tid; i < 512; i += 256) {
            int j = i >> 3, f = (i & 7) << 2;
            float4 v = *(const float4*)(w_in + (size_t)(j0 + j) * CIN + c0 + f);
            Ws[f + 0][j] = v.x; Ws[f + 1][j] = v.y;
            Ws[f + 2][j] = v.z; Ws[f + 3][j] = v.w;
        }
        __syncthreads();
#pragma unroll 8
        for (int k = 0; k < 32; k++) {
            float4 a = *(const float4*)&Xs[k][ty << 2];
            float4 w = *(const float4*)&Ws[k][tx << 2];
            float av[4] = {a.x, a.y, a.z, a.w};
            float wv[4] = {w.x, w.y, w.z, w.w};
#pragma unroll
            for (int u = 0; u < 4; u++)
#pragma unroll
                for (int v = 0; v < 4; v++) acc[u][v] += av[u] * wv[v];
        }
        __syncthreads();
    }

    // j-tile [j0, j0+64) lies entirely inside one of Q/K/G (128-wide buffers)
    float* dst = (j0 < 128) ? g_q : (j0 < 256) ? g_k : g_g;
    const int jj = (j0 & 127) + (tx << 2);
#pragma unroll
    for (int u = 0; u < 4; u++) {
        *(float4*)(dst + ((size_t)b * NTOK + n0 + (ty << 2) + u) * CRD + jj) =
            make_float4(acc[u][0], acc[u][1], acc[u][2], acc[u][3]);
    }
}

// ---------------------------------------------------------------------------
// Kernel 2: fused flash attention (fp32, online softmax).
// Block = (batch b, 64-query tile).  grid (64, 8), 256 threads.
// smem: Qs[c][i] 32KB, Ks[c][j] 32KB, Gs[j][c] 32KB, Ps[j][i] 16KB = 112KB.
// ---------------------------------------------------------------------------
__global__ __launch_bounds__(256) void attn_kernel() {
    extern __shared__ float sm[];
    float* Qs = sm;                    // [128][64]
    float* Ks = sm + 128 * 64;         // [128][64]
    float* Gs = sm + 2 * 128 * 64;     // [64][128]
    float* Ps = sm + 3 * 128 * 64;     // [64][64]

    const int q0 = blockIdx.x * 64;
    const int b  = blockIdx.y;
    const int tid = threadIdx.x;
    const int tx = tid & 15, ty = tid >> 4;

    // Load Q tile transposed: Qs[c][i]
    const float* Qg = g_q + ((size_t)b * NTOK + q0) * CRD;
#pragma unroll
    for (int it = 0; it < 8; it++) {
        int r = (tid >> 3) + ((it & 1) << 5);                 // row (token)
        int f = (((tid & 7) + ((it >> 1) << 3)) << 2);        // c offset
        float4 v = *(const float4*)(Qg + r * CRD + f);
        Qs[(f + 0) * 64 + r] = v.x; Qs[(f + 1) * 64 + r] = v.y;
        Qs[(f + 2) * 64 + r] = v.z; Qs[(f + 3) * 64 + r] = v.w;
    }

    float o[4][8];
    float mrow[4], lrow[4];
#pragma unroll
    for (int u = 0; u < 4; u++) {
        mrow[u] = -3.0e38f; lrow[u] = 0.f;
#pragma unroll
        for (int e = 0; e < 8; e++) o[u][e] = 0.f;
    }

    const float* Kg = g_k + (size_t)b * NTOK * CRD;
    const float* Gg = g_g + (size_t)b * NTOK * CRD;

    for (int kt = 0; kt < NTOK / 64; kt++) {
        const float* Kt = Kg + (size_t)kt * 64 * CRD;
        const float* Gt = Gg + (size_t)kt * 64 * CRD;
        __syncthreads();   // previous tile's GEMM2 readers done
        // Ks[c][j] (transposed load)
#pragma unroll
        for (int it = 0; it < 8; it++) {
            int r = (tid >> 3) + ((it & 1) << 5);
            int f = (((tid & 7) + ((it >> 1) << 3)) << 2);
            float4 v = *(const float4*)(Kt + r * CRD + f);
            Ks[(f + 0) * 64 + r] = v.x; Ks[(f + 1) * 64 + r] = v.y;
            Ks[(f + 2) * 64 + r] = v.z; Ks[(f + 3) * 64 + r] = v.w;
        }
        // Gs[j][c] (direct, coalesced)
        for (int i = tid; i < 2048; i += 256) {
            int j = i >> 5, f = (i & 31) << 2;
            *(float4*)(Gs + j * CRD + f) = *(const float4*)(Gt + j * CRD + f);
        }
        __syncthreads();

        // GEMM1: S[i][j] = sum_c Q[c][i] K[c][j]
        float s[4][4];
#pragma unroll
        for (int u = 0; u < 4; u++)
#pragma unroll
            for (int v = 0; v < 4; v++) s[u][v] = 0.f;
#pragma unroll 8
        for (int c = 0; c < CRD; c++) {
            float4 q = *(const float4*)(Qs + c * 64 + (ty << 2));
            float4 k = *(const float4*)(Ks + c * 64 + (tx << 2));
            float qv[4] = {q.x, q.y, q.z, q.w};
            float kv[4] = {k.x, k.y, k.z, k.w};
#pragma unroll
            for (int u = 0; u < 4; u++)
#pragma unroll
                for (int v = 0; v < 4; v++) s[u][v] += qv[u] * kv[v];
        }

        // Online softmax per row (row spread over 16 lanes of a half-warp)
#pragma unroll
        for (int u = 0; u < 4; u++) {
            float rmax = fmaxf(fmaxf(s[u][0], s[u][1]), fmaxf(s[u][2], s[u][3]));
#pragma unroll
            for (int off = 8; off > 0; off >>= 1)
                rmax = fmaxf(rmax, __shfl_xor_sync(0xffffffffu, rmax, off, 16));
            float mn = fmaxf(mrow[u], rmax);
            float corr = __expf(mrow[u] - mn);
            mrow[u] = mn;
            float psum = 0.f;
#pragma unroll
            for (int v = 0; v < 4; v++) {
                s[u][v] = __expf(s[u][v] - mn);
                psum += s[u][v];
            }
#pragma unroll
            for (int off = 8; off > 0; off >>= 1)
                psum += __shfl_xor_sync(0xffffffffu, psum, off, 16);
            lrow[u] = lrow[u] * corr + psum;
#pragma unroll
            for (int e = 0; e < 8; e++) o[u][e] *= corr;
#pragma unroll
            for (int v = 0; v < 4; v++)
                Ps[((tx << 2) + v) * 64 + (ty << 2) + u] = s[u][v];
        }
        __syncthreads();

        // GEMM2: O[i][c] += P[j][i] * G[j][c]
#pragma unroll 4
        for (int j = 0; j < 64; j++) {
            float4 pp = *(const float4*)(Ps + j * 64 + (ty << 2));
            float4 ga = *(const float4*)(Gs + j * CRD + (tx << 3));
            float4 gb = *(const float4*)(Gs + j * CRD + (tx << 3) + 4);
            float pv[4] = {pp.x, pp.y, pp.z, pp.w};
            float gv[8] = {ga.x, ga.y, ga.z, ga.w, gb.x, gb.y, gb.z, gb.w};
#pragma unroll
            for (int u = 0; u < 4; u++)
#pragma unroll
                for (int e = 0; e < 8; e++) o[u][e] += pv[u] * gv[e];
        }
    }

    // Epilogue: normalize and store Y[b][q0+i][c]
    float* Yg = g_y + ((size_t)b * NTOK + q0) * CRD;
#pragma unroll
    for (int u = 0; u < 4; u++) {
        float inv = 1.f / lrow[u];
        float* row = Yg + ((ty << 2) + u) * CRD + (tx << 3);
        *(float4*)(row)     = make_float4(o[u][0] * inv, o[u][1] * inv,
                                          o[u][2] * inv, o[u][3] * inv);
        *(float4*)(row + 4) = make_float4(o[u][4] * inv, o[u][5] * inv,
                                          o[u][6] * inv, o[u][7] * inv);
    }
}

// ---------------------------------------------------------------------------
// Kernel 3: output GEMM + residual. out[b,c,n] = x[b,c,n] + sum_k w_out[c,k] Y[b,n,k]
// Block tile 64c x 64n, full K=128 in smem.  grid (64, 8, 8).
// ---------------------------------------------------------------------------
__global__ __launch_bounds__(256) void out_kernel(const float* __restrict__ x,
                                                  const float* __restrict__ w_out,
                                                  float* __restrict__ out) {
    extern __shared__ float sm[];
    float* Wt = sm;          // [128][64]  (k, c)
    float* Yt = sm + 8192;   // [128][64]  (k, n)
    const int n0 = blockIdx.x * 64;
    const int c0 = blockIdx.y * 64;
    const int b  = blockIdx.z;
    const int tid = threadIdx.x;
    const int tx = tid & 15, ty = tid >> 4;

    const float* Wg = w_out + (size_t)c0 * CRD;
    const float* Yg = g_y + ((size_t)b * NTOK + n0) * CRD;
#pragma unroll
    for (int it = 0; it < 8; it++) {
        int r = (tid >> 3) + ((it & 1) << 5);
        int f = (((tid & 7) + ((it >> 1) << 3)) << 2);
        float4 v = *(const float4*)(Wg + r * CRD + f);
        Wt[(f + 0) * 64 + r] = v.x; Wt[(f + 1) * 64 + r] = v.y;
        Wt[(f + 2) * 64 + r] = v.z; Wt[(f + 3) * 64 + r] = v.w;
        float4 w2 = *(const float4*)(Yg + r * CRD + f);
        Yt[(f + 0) * 64 + r] = w2.x; Yt[(f + 1) * 64 + r] = w2.y;
        Yt[(f + 2) * 64 + r] = w2.z; Yt[(f + 3) * 64 + r] = w2.w;
    }
    __syncthreads();

    float acc[4][4];
#pragma unroll
    for (int u = 0; u < 4; u++)
#pragma unroll
        for (int v = 0; v < 4; v++) acc[u][v] = 0.f;

#pragma unroll 8
    for (int k = 0; k < CRD; k++) {
        float4 a  = *(const float4*)(Wt + k * 64 + (ty << 2));
        float4 yv = *(const float4*)(Yt + k * 64 + (tx << 2));
        float av[4] = {a.x, a.y, a.z, a.w};
        float bv[4] = {yv.x, yv.y, yv.z, yv.w};
#pragma unroll
        for (int u = 0; u < 4; u++)
#pragma unroll
            for (int v = 0; v < 4; v++) acc[u][v] += av[u] * bv[v];
    }

#pragma unroll
    for (int u = 0; u < 4; u++) {
        size_t off = ((size_t)b * CIN + c0 + (ty << 2) + u) * NTOK + n0 + (tx << 2);
        float4 xv = *(const float4*)(x + off);
        *(float4*)(out + off) = make_float4(xv.x + acc[u][0], xv.y + acc[u][1],
                                            xv.z + acc[u][2], xv.w + acc[u][3]);
    }
}

// ---------------------------------------------------------------------------
extern "C" void kernel_launch(void* const* d_in, const int* in_sizes, int n_in,
                              void* d_out, int out_size) {
    const float* x = nullptr; const float* w_in = nullptr; const float* w_out = nullptr;
    for (int i = 0; i < n_in; i++) {
        if (in_sizes[i] == BATCH * CIN * NTOK)      x     = (const float*)d_in[i];
        else if (in_sizes[i] == 3 * CRD * CIN)      w_in  = (const float*)d_in[i];
        else if (in_sizes[i] == CIN * CRD)          w_out = (const float*)d_in[i];
    }

    static int attr_done = 0;
    if (!attr_done) {
        cudaFuncSetAttribute(attn_kernel,
                             cudaFuncAttributeMaxDynamicSharedMemorySize, 114688);
        cudaFuncSetAttribute(attn_kernel,
                             cudaFuncAttributePreferredSharedMemoryCarveout, 100);
        cudaFuncSetAttribute(out_kernel,
                             cudaFuncAttributeMaxDynamicSharedMemorySize, 65536);
        attr_done = 1;
    }

    proj_kernel<<<dim3(64, 6, 8), 256>>>(x, w_in);
    attn_kernel<<<dim3(64, 8), 256, 114688>>>();
    out_kernel<<<dim3(64, 8, 8), 256, 65536>>>(x, w_out, (float*)d_out);
}

// round 3
// speedup vs baseline: 2.8475x; 2.8475x over previous
#include <cuda_runtime.h>
#include <cstdint>

// NonLocalBlock: B=8, C=512, H=W=64 -> N=4096, CR=128
//   proj  = w_in[384,512] @ x[b,512,4096]        -> Q,K,G  [b,4096,128] (token-major)
//   attn  = flash-style softmax(Q K^T) G (tf32 tensor cores) -> Y [b,4096,128]
//   out   = x + w_out[512,128] @ Y^T             -> [b,512,4096]

#define BATCH 8
#define CIN   512
#define NTOK  4096
#define CRD   128

__device__ float g_q[(size_t)BATCH * NTOK * CRD];
__device__ float g_k[(size_t)BATCH * NTOK * CRD];
__device__ float g_g[(size_t)BATCH * NTOK * CRD];
__device__ float g_y[(size_t)BATCH * NTOK * CRD];

// ---------------------------------------------------------------------------
// Kernel 1: projection GEMM (unchanged, known-good).
// ---------------------------------------------------------------------------
__global__ __launch_bounds__(256) void proj_kernel(const float* __restrict__ x,
                                                   const float* __restrict__ w_in) {
    __shared__ float Xs[32][64];
    __shared__ float Ws[32][64];
    const int n0 = blockIdx.x * 64;
    const int j0 = blockIdx.y * 64;
    const int b  = blockIdx.z;
    const int tid = threadIdx.x;
    const int tx = tid & 15, ty = tid >> 4;

    const float* xb = x + (size_t)b * CIN * NTOK + n0;

    float acc[4][4];
#pragma unroll
    for (int u = 0; u < 4; u++)
#pragma unroll
        for (int v = 0; v < 4; v++) acc[u][v] = 0.f;

    for (int c0 = 0; c0 < CIN; c0 += 32) {
        for (int i = tid; i < 512; i += 256) {
            int k = i >> 4, f = (i & 15) << 2;
            *(float4*)&Xs[k][f] =
                *(const float4*)(xb + (size_t)(c0 + k) * NTOK + f);
        }
        for (int i = tid; i < 512; i += 256) {
            int j = i >> 3, f = (i & 7) << 2;
            float4 v = *(const float4*)(w_in + (size_t)(j0 + j) * CIN + c0 + f);
            Ws[f + 0][j] = v.x; Ws[f + 1][j] = v.y;
            Ws[f + 2][j] = v.z; Ws[f + 3][j] = v.w;
        }
        __syncthreads();
#pragma unroll 8
        for (int k = 0; k < 32; k++) {
            float4 a = *(const float4*)&Xs[k][ty << 2];
            float4 w = *(const float4*)&Ws[k][tx << 2];
            float av[4] = {a.x, a.y, a.z, a.w};
            float wv[4] = {w.x, w.y, w.z, w.w};
#pragma unroll
            for (int u = 0; u < 4; u++)
#pragma unroll
                for (int v = 0; v < 4; v++) acc[u][v] += av[u] * wv[v];
        }
        __syncthreads();
    }

    float* dst = (j0 < 128) ? g_q : (j0 < 256) ? g_k : g_g;
    const int jj = (j0 & 127) + (tx << 2);
#pragma unroll
    for (int u = 0; u < 4; u++) {
        *(float4*)(dst + ((size_t)b * NTOK + n0 + (ty << 2) + u) * CRD + jj) =
            make_float4(acc[u][0], acc[u][1], acc[u][2], acc[u][3]);
    }
}

// ---------------------------------------------------------------------------
// tf32 mma.sync m16n8k8 wrapper.  A row-major (regs), B col-major (regs),
// C/D fp32.  fp32 bits fed directly as tf32 (HW truncates mantissa).
// ---------------------------------------------------------------------------
__device__ __forceinline__ void mma_tf32(float d[4], const uint32_t a[4],
                                         uint32_t b0, uint32_t b1,
                                         const float c[4]) {
    asm volatile(
        "mma.sync.aligned.m16n8k8.row.col.f32.tf32.tf32.f32 "
        "{%0,%1,%2,%3}, {%4,%5,%6,%7}, {%8,%9}, {%10,%11,%12,%13};\n"
        : "=f"(d[0]), "=f"(d[1]), "=f"(d[2]), "=f"(d[3])
        : "r"(a[0]), "r"(a[1]), "r"(a[2]), "r"(a[3]),
          "r"(b0), "r"(b1),
          "f"(c[0]), "f"(c[1]), "f"(c[2]), "f"(c[3]));
}

// ---------------------------------------------------------------------------
// Kernel 2: flash attention on tf32 tensor cores.
// CTA = 128 q-rows (8 warps x 16), kv tiles of 64, grid (32, 8), 256 thr.
// smem: Ks[64][132] 33792B + Gs[64][136] 34816B + Ps[8][16][68] 34816B = 100.9KB
// Bank math: Ks row stride 132 (mod32=4) -> GEMM1 B-frag loads conflict-free
//            Gs row stride 136 (mod32=8) -> GEMM2 B-frag loads conflict-free
//            Ps row stride  68 (mod32=4) -> A-frag loads conflict-free
// ---------------------------------------------------------------------------
#define KS_STRIDE 132
#define GS_STRIDE 136
#define PS_STRIDE 68

__global__ __launch_bounds__(256, 1) void attn_tc_kernel() {
    extern __shared__ float smf[];
    float* Ks = smf;                                   // [64][132]
    float* Gs = smf + 64 * KS_STRIDE;                  // [64][136]
    float* Ps = smf + 64 * KS_STRIDE + 64 * GS_STRIDE; // [8][16][68]

    const int q0  = blockIdx.x * 128;
    const int b   = blockIdx.y;
    const int tid = threadIdx.x;
    const int w    = tid >> 5;
    const int lane = tid & 31;
    const int gp = lane >> 2;   // groupID   (row within fragment)
    const int tg = lane & 3;    // threadID_in_group (col/k within fragment)

    // Q fragments held in registers: 16 k-steps x 4 regs (rows gp, gp+8)
    const float* Qg = g_q + ((size_t)b * NTOK + q0 + w * 16) * CRD;
    uint32_t qf[16][4];
#pragma unroll
    for (int t = 0; t < 16; t++) {
        qf[t][0] = __float_as_uint(Qg[gp * CRD + t * 8 + tg]);
        qf[t][1] = __float_as_uint(Qg[(gp + 8) * CRD + t * 8 + tg]);
        qf[t][2] = __float_as_uint(Qg[gp * CRD + t * 8 + tg + 4]);
        qf[t][3] = __float_as_uint(Qg[(gp + 8) * CRD + t * 8 + tg + 4]);
    }

    float o[16][4];
#pragma unroll
    for (int j = 0; j < 16; j++)
#pragma unroll
        for (int e = 0; e < 4; e++) o[j][e] = 0.f;
    float m0 = -3.0e38f, m1 = -3.0e38f, l0 = 0.f, l1 = 0.f;

    const float* Kg = g_k + (size_t)b * NTOK * CRD;
    const float* Gg = g_g + (size_t)b * NTOK * CRD;
    float* Pw = Ps + w * 16 * PS_STRIDE;

    for (int kt = 0; kt < NTOK / 64; kt++) {
        const float* Kt = Kg + (size_t)kt * 64 * CRD;
        const float* Gt = Gg + (size_t)kt * 64 * CRD;
        __syncthreads();   // previous iteration's Ks/Gs readers done
        // Cooperative tile load: 64 rows x 128 cols each, float4, coalesced.
#pragma unroll
        for (int i = 0; i < 8; i++) {
            int idx = i * 256 + tid;          // 0..2047
            int r = idx >> 5, c4 = (idx & 31) << 2;
            *(float4*)(Ks + r * KS_STRIDE + c4) =
                *(const float4*)(Kt + r * CRD + c4);
            *(float4*)(Gs + r * GS_STRIDE + c4) =
                *(const float4*)(Gt + r * CRD + c4);
        }
        __syncthreads();

        // GEMM1: S[16q x 64kv] = Q x K^T   (8 n-tiles, 16 k-steps)
        float s[8][4];
#pragma unroll
        for (int j = 0; j < 8; j++)
#pragma unroll
            for (int e = 0; e < 4; e++) s[j][e] = 0.f;
#pragma unroll
        for (int t = 0; t < 16; t++) {
#pragma unroll
            for (int j = 0; j < 8; j++) {
                uint32_t b0 = __float_as_uint(
                    Ks[(j * 8 + gp) * KS_STRIDE + t * 8 + tg]);
                uint32_t b1 = __float_as_uint(
                    Ks[(j * 8 + gp) * KS_STRIDE + t * 8 + tg + 4]);
                mma_tf32(s[j], qf[t], b0, b1, s[j]);
            }
        }

        // Online softmax.  Thread owns rows gp (via s[.][0..1]) and gp+8
        // (s[.][2..3]); each row spread over the 4 lanes of a quad.
        float mx0 = -3.0e38f, mx1 = -3.0e38f;
#pragma unroll
        for (int j = 0; j < 8; j++) {
            mx0 = fmaxf(mx0, fmaxf(s[j][0], s[j][1]));
            mx1 = fmaxf(mx1, fmaxf(s[j][2], s[j][3]));
        }
        mx0 = fmaxf(mx0, __shfl_xor_sync(0xffffffffu, mx0, 1));
        mx0 = fmaxf(mx0, __shfl_xor_sync(0xffffffffu, mx0, 2));
        mx1 = fmaxf(mx1, __shfl_xor_sync(0xffffffffu, mx1, 1));
        mx1 = fmaxf(mx1, __shfl_xor_sync(0xffffffffu, mx1, 2));
        float nm0 = fmaxf(m0, mx0), nm1 = fmaxf(m1, mx1);
        float corr0 = __expf(m0 - nm0), corr1 = __expf(m1 - nm1);
        m0 = nm0; m1 = nm1;
        float ps0 = 0.f, ps1 = 0.f;
#pragma unroll
        for (int j = 0; j < 8; j++) {
            s[j][0] = __expf(s[j][0] - nm0);
            s[j][1] = __expf(s[j][1] - nm0);
            s[j][2] = __expf(s[j][2] - nm1);
            s[j][3] = __expf(s[j][3] - nm1);
            ps0 += s[j][0] + s[j][1];
            ps1 += s[j][2] + s[j][3];
        }
        ps0 += __shfl_xor_sync(0xffffffffu, ps0, 1);
        ps0 += __shfl_xor_sync(0xffffffffu, ps0, 2);
        ps1 += __shfl_xor_sync(0xffffffffu, ps1, 1);
        ps1 += __shfl_xor_sync(0xffffffffu, ps1, 2);
        l0 = l0 * corr0 + ps0;
        l1 = l1 * corr1 + ps1;
#pragma unroll
        for (int j = 0; j < 16; j++) {
            o[j][0] *= corr0; o[j][1] *= corr0;
            o[j][2] *= corr1; o[j][3] *= corr1;
        }

        // P -> smem (C-frag layout to row-major), warp-private region.
#pragma unroll
        for (int j = 0; j < 8; j++) {
            *(float2*)&Pw[gp * PS_STRIDE + j * 8 + 2 * tg] =
                make_float2(s[j][0], s[j][1]);
            *(float2*)&Pw[(gp + 8) * PS_STRIDE + j * 8 + 2 * tg] =
                make_float2(s[j][2], s[j][3]);
        }
        __syncwarp();

        // GEMM2: O[16q x 128c] += P[16q x 64kv] x G[64kv x 128c]
#pragma unroll
        for (int ss = 0; ss < 8; ss++) {
            uint32_t a[4];
            a[0] = __float_as_uint(Pw[gp * PS_STRIDE + ss * 8 + tg]);
            a[1] = __float_as_uint(Pw[(gp + 8) * PS_STRIDE + ss * 8 + tg]);
            a[2] = __float_as_uint(Pw[gp * PS_STRIDE + ss * 8 + tg + 4]);
            a[3] = __float_as_uint(Pw[(gp + 8) * PS_STRIDE + ss * 8 + tg + 4]);
#pragma unroll
            for (int j2 = 0; j2 < 16; j2++) {
                uint32_t b0 = __float_as_uint(
                    Gs[(ss * 8 + tg) * GS_STRIDE + j2 * 8 + gp]);
                uint32_t b1 = __float_as_uint(
                    Gs[(ss * 8 + tg + 4) * GS_STRIDE + j2 * 8 + gp]);
                mma_tf32(o[j2], a, b0, b1, o[j2]);
            }
        }
        __syncwarp();   // P reads done before next iteration overwrites
    }

    // Epilogue: normalize, store Y (fragment rows gp / gp+8).
    const float inv0 = 1.f / l0, inv1 = 1.f / l1;
    float* Yg = g_y + ((size_t)b * NTOK + q0 + w * 16) * CRD;
#pragma unroll
    for (int j2 = 0; j2 < 16; j2++) {
        *(float2*)&Yg[gp * CRD + j2 * 8 + 2 * tg] =
            make_float2(o[j2][0] * inv0, o[j2][1] * inv0);
        *(float2*)&Yg[(gp + 8) * CRD + j2 * 8 + 2 * tg] =
            make_float2(o[j2][2] * inv1, o[j2][3] * inv1);
    }
}

// ---------------------------------------------------------------------------
// Kernel 3: output GEMM + residual (unchanged, known-good).
// ---------------------------------------------------------------------------
__global__ __launch_bounds__(256) void out_kernel(const float* __restrict__ x,
                                                  const float* __restrict__ w_out,
                                                  float* __restrict__ out) {
    extern __shared__ float sm[];
    float* Wt = sm;
    float* Yt = sm + 8192;
    const int n0 = blockIdx.x * 64;
    const int c0 = blockIdx.y * 64;
    const int b  = blockIdx.z;
    const int tid = threadIdx.x;
    const int tx = tid & 15, ty = tid >> 4;

    const float* Wg = w_out + (size_t)c0 * CRD;
    const float* Yg = g_y + ((size_t)b * NTOK + n0) * CRD;
#pragma unroll
    for (int it = 0; it < 8; it++) {
        int r = (tid >> 3) + ((it & 1) << 5);
        int f = (((tid & 7) + ((it >> 1) << 3)) << 2);
        float4 v = *(const float4*)(Wg + r * CRD + f);
        Wt[(f + 0) * 64 + r] = v.x; Wt[(f + 1) * 64 + r] = v.y;
        Wt[(f + 2) * 64 + r] = v.z; Wt[(f + 3) * 64 + r] = v.w;
        float4 w2 = *(const float4*)(Yg + r * CRD + f);
        Yt[(f + 0) * 64 + r] = w2.x; Yt[(f + 1) * 64 + r] = w2.y;
        Yt[(f + 2) * 64 + r] = w2.z; Yt[(f + 3) * 64 + r] = w2.w;
    }
    __syncthreads();

    float acc[4][4];
#pragma unroll
    for (int u = 0; u < 4; u++)
#pragma unroll
        for (int v = 0; v < 4; v++) acc[u][v] = 0.f;

#pragma unroll 8
    for (int k = 0; k < CRD; k++) {
        float4 a  = *(const float4*)(Wt + k * 64 + (ty << 2));
        float4 yv = *(const float4*)(Yt + k * 64 + (tx << 2));
        float av[4] = {a.x, a.y, a.z, a.w};
        float bv[4] = {yv.x, yv.y, yv.z, yv.w};
#pragma unroll
        for (int u = 0; u < 4; u++)
#pragma unroll
            for (int v = 0; v < 4; v++) acc[u][v] += av[u] * bv[v];
    }

#pragma unroll
    for (int u = 0; u < 4; u++) {
        size_t off = ((size_t)b * CIN + c0 + (ty << 2) + u) * NTOK + n0 + (tx << 2);
        float4 xv = *(const float4*)(x + off);
        *(float4*)(out + off) = make_float4(xv.x + acc[u][0], xv.y + acc[u][1],
                                            xv.z + acc[u][2], xv.w + acc[u][3]);
    }
}

// ---------------------------------------------------------------------------
extern "C" void kernel_launch(void* const* d_in, const int* in_sizes, int n_in,
                              void* d_out, int out_size) {
    const float* x = nullptr; const float* w_in = nullptr; const float* w_out = nullptr;
    for (int i = 0; i < n_in; i++) {
        if (in_sizes[i] == BATCH * CIN * NTOK)      x     = (const float*)d_in[i];
        else if (in_sizes[i] == 3 * CRD * CIN)      w_in  = (const float*)d_in[i];
        else if (in_sizes[i] == CIN * CRD)          w_out = (const float*)d_in[i];
    }

    const int attn_smem = (64 * KS_STRIDE + 64 * GS_STRIDE + 8 * 16 * PS_STRIDE)
                          * (int)sizeof(float);   // 103,424 B

    static int attr_done = 0;
    if (!attr_done) {
        cudaFuncSetAttribute(attn_tc_kernel,
                             cudaFuncAttributeMaxDynamicSharedMemorySize, attn_smem);
        cudaFuncSetAttribute(attn_tc_kernel,
                             cudaFuncAttributePreferredSharedMemoryCarveout, 100);
        cudaFuncSetAttribute(out_kernel,
                             cudaFuncAttributeMaxDynamicSharedMemorySize, 65536);
        attr_done = 1;
    }

    proj_kernel<<<dim3(64, 6, 8), 256>>>(x, w_in);
    attn_tc_kernel<<<dim3(32, 8), 256, attn_smem>>>();
    out_kernel<<<dim3(64, 8, 8), 256, 65536>>>(x, w_out, (float*)d_out);
}

// round 5
// speedup vs baseline: 4.4226x; 1.5532x over previous
#include <cuda_runtime.h>
#include <cstdint>

// NonLocalBlock: B=8, C=512, H=W=64 -> N=4096, CR=128
//   proj  = w_in[384,512] @ x[b,512,4096]   (tf32 TC) -> Q,K,G [b,4096,128]
//   attn  = flash softmax(Q K^T) G          (tf32 TC) -> Y     [b,4096,128]
//   out   = x + w_out[512,128] @ Y^T        (tf32 TC) -> [b,512,4096]

#define BATCH 8
#define CIN   512
#define NTOK  4096
#define CRD   128

__device__ float g_q[(size_t)BATCH * NTOK * CRD];
__device__ float g_k[(size_t)BATCH * NTOK * CRD];
__device__ float g_g[(size_t)BATCH * NTOK * CRD];
__device__ float g_y[(size_t)BATCH * NTOK * CRD];

// ---------------------------------------------------------------------------
// tf32 mma.sync m16n8k8: A row-major regs, B col-major regs, C/D fp32.
// Validated fragment layout (R3 pass):
//   A: a0=[gp][tg] a1=[gp+8][tg] a2=[gp][tg+4] a3=[gp+8][tg+4]
//   B: b0=[k=tg][col=gp] b1=[k=tg+4][col=gp]
//   C: c0=[gp][2tg] c1=[gp][2tg+1] c2=[gp+8][2tg] c3=[gp+8][2tg+1]
// ---------------------------------------------------------------------------
__device__ __forceinline__ void mma_tf32(float d[4], const uint32_t a[4],
                                         uint32_t b0, uint32_t b1,
                                         const float c[4]) {
    asm volatile(
        "mma.sync.aligned.m16n8k8.row.col.f32.tf32.tf32.f32 "
        "{%0,%1,%2,%3}, {%4,%5,%6,%7}, {%8,%9}, {%10,%11,%12,%13};\n"
        : "=f"(d[0]), "=f"(d[1]), "=f"(d[2]), "=f"(d[3])
        : "r"(a[0]), "r"(a[1]), "r"(a[2]), "r"(a[3]),
          "r"(b0), "r"(b1),
          "f"(c[0]), "f"(c[1]), "f"(c[2]), "f"(c[3]));
}

// ---------------------------------------------------------------------------
// Kernel 1: projection GEMM on tensor cores.
// CTA: 128 tokens x 128 features, K=512 in chunks of 32.  grid (32, 3, 8).
// Warp grid 4(m) x 2(n): warp = 32 tok x 64 feat = 2 m-tiles x 8 n-tiles.
// smem: Xs[32][136] (c,token) + Ws[128][36] (j,c-chunk) = 35.8 KB.
// Bank math: Xs A-frag (8tg+gp)%32 distinct; Ws B-frag (4gp+tg)%32 distinct.
// ---------------------------------------------------------------------------
#define XS_S 136
#define WJ_S 36

__global__ __launch_bounds__(256) void proj_tc_kernel(const float* __restrict__ x,
                                                      const float* __restrict__ w_in) {
    __shared__ float Xs[32 * XS_S];   // [c][token]
    __shared__ float Ws[128 * WJ_S];  // [j][c]
    const int n0 = blockIdx.x * 128;
    const int j0 = blockIdx.y * 128;
    const int b  = blockIdx.z;
    const int tid  = threadIdx.x;
    const int w    = tid >> 5;
    const int lane = tid & 31;
    const int gp = lane >> 2, tg = lane & 3;
    const int wm = w & 3;    // token subtile (32 tokens)
    const int wn = w >> 2;   // feature subtile (64 features)

    const float* xb = x + (size_t)b * CIN * NTOK + n0;
    const float* wb = w_in + (size_t)j0 * CIN;

    float acc[2][8][4];
#pragma unroll
    for (int mt = 0; mt < 2; mt++)
#pragma unroll
        for (int nt = 0; nt < 8; nt++)
#pragma unroll
            for (int e = 0; e < 4; e++) acc[mt][nt][e] = 0.f;

    for (int c0 = 0; c0 < CIN; c0 += 32) {
        __syncthreads();
        // Xs[k][n] direct: rows 32 (c), cols 128 tokens, float4 coalesced.
#pragma unroll
        for (int i = 0; i < 4; i++) {
            int idx = i * 256 + tid;           // 0..1023
            int r = idx >> 5, c4 = (idx & 31) << 2;
            *(float4*)&Xs[r * XS_S + c4] =
                *(const float4*)(xb + (size_t)(c0 + r) * NTOK + c4);
        }
        // Ws[j][k] direct (no transpose): 128 rows (j), 32 cols (c-chunk).
#pragma unroll
        for (int i = 0; i < 4; i++) {
            int idx = i * 256 + tid;
            int j = idx >> 3, f4 = (idx & 7) << 2;
            *(float4*)&Ws[j * WJ_S + f4] =
                *(const float4*)(wb + (size_t)j * CIN + c0 + f4);
        }
        __syncthreads();

#pragma unroll
        for (int kk = 0; kk < 4; kk++) {
            uint32_t a[2][4];
#pragma unroll
            for (int mt = 0; mt < 2; mt++) {
                int m = wm * 32 + mt * 16;
                a[mt][0] = __float_as_uint(Xs[(kk * 8 + tg) * XS_S + m + gp]);
                a[mt][1] = __float_as_uint(Xs[(kk * 8 + tg) * XS_S + m + gp + 8]);
                a[mt][2] = __float_as_uint(Xs[(kk * 8 + tg + 4) * XS_S + m + gp]);
                a[mt][3] = __float_as_uint(Xs[(kk * 8 + tg + 4) * XS_S + m + gp + 8]);
            }
#pragma unroll
            for (int nt = 0; nt < 8; nt++) {
                int j = wn * 64 + nt * 8;
                uint32_t b0 = __float_as_uint(Ws[(j + gp) * WJ_S + kk * 8 + tg]);
                uint32_t b1 = __float_as_uint(Ws[(j + gp) * WJ_S + kk * 8 + tg + 4]);
                mma_tf32(acc[0][nt], a[0], b0, b1, acc[0][nt]);
                mma_tf32(acc[1][nt], a[1], b0, b1, acc[1][nt]);
            }
        }
    }

    float* dst = (j0 == 0) ? g_q : (j0 == 128) ? g_k : g_g;
    float* base = dst + ((size_t)b * NTOK + n0 + wm * 32) * CRD + wn * 64;
#pragma unroll
    for (int mt = 0; mt < 2; mt++)
#pragma unroll
        for (int nt = 0; nt < 8; nt++) {
            *(float2*)&base[(mt * 16 + gp) * CRD + nt * 8 + 2 * tg] =
                make_float2(acc[mt][nt][0], acc[mt][nt][1]);
            *(float2*)&base[(mt * 16 + gp + 8) * CRD + nt * 8 + 2 * tg] =
                make_float2(acc[mt][nt][2], acc[mt][nt][3]);
        }
}

// ---------------------------------------------------------------------------
// Kernel 2: flash attention on tf32 tensor cores (unchanged, validated R3).
// ---------------------------------------------------------------------------
#define KS_STRIDE 132
#define GS_STRIDE 136
#define PS_STRIDE 68

__global__ __launch_bounds__(256, 1) void attn_tc_kernel() {
    extern __shared__ float smf[];
    float* Ks = smf;                                   // [64][132]
    float* Gs = smf + 64 * KS_STRIDE;                  // [64][136]
    float* Ps = smf + 64 * KS_STRIDE + 64 * GS_STRIDE; // [8][16][68]

    const int q0  = blockIdx.x * 128;
    const int b   = blockIdx.y;
    const int tid = threadIdx.x;
    const int w    = tid >> 5;
    const int lane = tid & 31;
    const int gp = lane >> 2;
    const int tg = lane & 3;

    const float* Qg = g_q + ((size_t)b * NTOK + q0 + w * 16) * CRD;
    uint32_t qf[16][4];
#pragma unroll
    for (int t = 0; t < 16; t++) {
        qf[t][0] = __float_as_uint(Qg[gp * CRD + t * 8 + tg]);
        qf[t][1] = __float_as_uint(Qg[(gp + 8) * CRD + t * 8 + tg]);
        qf[t][2] = __float_as_uint(Qg[gp * CRD + t * 8 + tg + 4]);
        qf[t][3] = __float_as_uint(Qg[(gp + 8) * CRD + t * 8 + tg + 4]);
    }

    float o[16][4];
#pragma unroll
    for (int j = 0; j < 16; j++)
#pragma unroll
        for (int e = 0; e < 4; e++) o[j][e] = 0.f;
    float m0 = -3.0e38f, m1 = -3.0e38f, l0 = 0.f, l1 = 0.f;

    const float* Kg = g_k + (size_t)b * NTOK * CRD;
    const float* Gg = g_g + (size_t)b * NTOK * CRD;
    float* Pw = Ps + w * 16 * PS_STRIDE;

    for (int kt = 0; kt < NTOK / 64; kt++) {
        const float* Kt = Kg + (size_t)kt * 64 * CRD;
        const float* Gt = Gg + (size_t)kt * 64 * CRD;
        __syncthreads();
#pragma unroll
        for (int i = 0; i < 8; i++) {
            int idx = i * 256 + tid;
            int r = idx >> 5, c4 = (idx & 31) << 2;
            *(float4*)(Ks + r * KS_STRIDE + c4) =
                *(const float4*)(Kt + r * CRD + c4);
            *(float4*)(Gs + r * GS_STRIDE + c4) =
                *(const float4*)(Gt + r * CRD + c4);
        }
        __syncthreads();

        float s[8][4];
#pragma unroll
        for (int j = 0; j < 8; j++)
#pragma unroll
            for (int e = 0; e < 4; e++) s[j][e] = 0.f;
#pragma unroll
        for (int t = 0; t < 16; t++) {
#pragma unroll
            for (int j = 0; j < 8; j++) {
                uint32_t b0 = __float_as_uint(
                    Ks[(j * 8 + gp) * KS_STRIDE + t * 8 + tg]);
                uint32_t b1 = __float_as_uint(
                    Ks[(j * 8 + gp) * KS_STRIDE + t * 8 + tg + 4]);
                mma_tf32(s[j], qf[t], b0, b1, s[j]);
            }
        }

        float mx0 = -3.0e38f, mx1 = -3.0e38f;
#pragma unroll
        for (int j = 0; j < 8; j++) {
            mx0 = fmaxf(mx0, fmaxf(s[j][0], s[j][1]));
            mx1 = fmaxf(mx1, fmaxf(s[j][2], s[j][3]));
        }
        mx0 = fmaxf(mx0, __shfl_xor_sync(0xffffffffu, mx0, 1));
        mx0 = fmaxf(mx0, __shfl_xor_sync(0xffffffffu, mx0, 2));
        mx1 = fmaxf(mx1, __shfl_xor_sync(0xffffffffu, mx1, 1));
        mx1 = fmaxf(mx1, __shfl_xor_sync(0xffffffffu, mx1, 2));
        float nm0 = fmaxf(m0, mx0), nm1 = fmaxf(m1, mx1);
        float corr0 = __expf(m0 - nm0), corr1 = __expf(m1 - nm1);
        m0 = nm0; m1 = nm1;
        float ps0 = 0.f, ps1 = 0.f;
#pragma unroll
        for (int j = 0; j < 8; j++) {
            s[j][0] = __expf(s[j][0] - nm0);
            s[j][1] = __expf(s[j][1] - nm0);
            s[j][2] = __expf(s[j][2] - nm1);
            s[j][3] = __expf(s[j][3] - nm1);
            ps0 += s[j][0] + s[j][1];
            ps1 += s[j][2] + s[j][3];
        }
        ps0 += __shfl_xor_sync(0xffffffffu, ps0, 1);
        ps0 += __shfl_xor_sync(0xffffffffu, ps0, 2);
        ps1 += __shfl_xor_sync(0xffffffffu, ps1, 1);
        ps1 += __shfl_xor_sync(0xffffffffu, ps1, 2);
        l0 = l0 * corr0 + ps0;
        l1 = l1 * corr1 + ps1;
#pragma unroll
        for (int j = 0; j < 16; j++) {
            o[j][0] *= corr0; o[j][1] *= corr0;
            o[j][2] *= corr1; o[j][3] *= corr1;
        }

#pragma unroll
        for (int j = 0; j < 8; j++) {
            *(float2*)&Pw[gp * PS_STRIDE + j * 8 + 2 * tg] =
                make_float2(s[j][0], s[j][1]);
            *(float2*)&Pw[(gp + 8) * PS_STRIDE + j * 8 + 2 * tg] =
                make_float2(s[j][2], s[j][3]);
        }
        __syncwarp();

#pragma unroll
        for (int ss = 0; ss < 8; ss++) {
            uint32_t a[4];
            a[0] = __float_as_uint(Pw[gp * PS_STRIDE + ss * 8 + tg]);
            a[1] = __float_as_uint(Pw[(gp + 8) * PS_STRIDE + ss * 8 + tg]);
            a[2] = __float_as_uint(Pw[gp * PS_STRIDE + ss * 8 + tg + 4]);
            a[3] = __float_as_uint(Pw[(gp + 8) * PS_STRIDE + ss * 8 + tg + 4]);
#pragma unroll
            for (int j2 = 0; j2 < 16; j2++) {
                uint32_t b0 = __float_as_uint(
                    Gs[(ss * 8 + tg) * GS_STRIDE + j2 * 8 + gp]);
                uint32_t b1 = __float_as_uint(
                    Gs[(ss * 8 + tg + 4) * GS_STRIDE + j2 * 8 + gp]);
                mma_tf32(o[j2], a, b0, b1, o[j2]);
            }
        }
        __syncwarp();
    }

    const float inv0 = 1.f / l0, inv1 = 1.f / l1;
    float* Yg = g_y + ((size_t)b * NTOK + q0 + w * 16) * CRD;
#pragma unroll
    for (int j2 = 0; j2 < 16; j2++) {
        *(float2*)&Yg[gp * CRD + j2 * 8 + 2 * tg] =
            make_float2(o[j2][0] * inv0, o[j2][1] * inv0);
        *(float2*)&Yg[(gp + 8) * CRD + j2 * 8 + 2 * tg] =
            make_float2(o[j2][2] * inv1, o[j2][3] * inv1);
    }
}

// ---------------------------------------------------------------------------
// Kernel 3: output GEMM + residual on tensor cores.
// CTA: 128 c-rows x 128 tokens, K=128 in chunks of 32.  grid (32, 4, 8).
// smem: As[128][36] (c,k) + Bs[128][36] (n,k) = 36.9 KB.
// ---------------------------------------------------------------------------
#define OA_S 36

__global__ __launch_bounds__(256) void out_tc_kernel(const float* __restrict__ x,
                                                     const float* __restrict__ w_out,
                                                     float* __restrict__ out) {
    __shared__ float As[128 * OA_S];  // [c][k]
    __shared__ float Bs[128 * OA_S];  // [n][k]
    const int n0 = blockIdx.x * 128;
    const int c0 = blockIdx.y * 128;
    const int b  = blockIdx.z;
    const int tid  = threadIdx.x;
    const int w    = tid >> 5;
    const int lane = tid & 31;
    const int gp = lane >> 2, tg = lane & 3;
    const int wm = w & 3;    // c subtile (32 rows)
    const int wn = w >> 2;   // n subtile (64 cols)

    const float* Wg = w_out + (size_t)c0 * CRD;
    const float* Yg = g_y + ((size_t)b * NTOK + n0) * CRD;

    float acc[2][8][4];
#pragma unroll
    for (int mt = 0; mt < 2; mt++)
#pragma unroll
        for (int nt = 0; nt < 8; nt++)
#pragma unroll
            for (int e = 0; e < 4; e++) acc[mt][nt][e] = 0.f;

    for (int k0 = 0; k0 < CRD; k0 += 32) {
        __syncthreads();
#pragma unroll
        for (int i = 0; i < 4; i++) {
            int idx = i * 256 + tid;
            int r = idx >> 3, f4 = (idx & 7) << 2;
            *(float4*)&As[r * OA_S + f4] =
                *(const float4*)(Wg + (size_t)r * CRD + k0 + f4);
            *(float4*)&Bs[r * OA_S + f4] =
                *(const float4*)(Yg + (size_t)r * CRD + k0 + f4);
        }
        __syncthreads();

#pragma unroll
        for (int kk = 0; kk < 4; kk++) {
            uint32_t a[2][4];
#pragma unroll
            for (int mt = 0; mt < 2; mt++) {
                int c = wm * 32 + mt * 16;
                a[mt][0] = __float_as_uint(As[(c + gp) * OA_S + kk * 8 + tg]);
                a[mt][1] = __float_as_uint(As[(c + gp + 8) * OA_S + kk * 8 + tg]);
                a[mt][2] = __float_as_uint(As[(c + gp) * OA_S + kk * 8 + tg + 4]);
                a[mt][3] = __float_as_uint(As[(c + gp + 8) * OA_S + kk * 8 + tg + 4]);
            }
#pragma unroll
            for (int nt = 0; nt < 8; nt++) {
                int n = wn * 64 + nt * 8;
                uint32_t b0 = __float_as_uint(Bs[(n + gp) * OA_S + kk * 8 + tg]);
                uint32_t b1 = __float_as_uint(Bs[(n + gp) * OA_S + kk * 8 + tg + 4]);
                mma_tf32(acc[0][nt], a[0], b0, b1, acc[0][nt]);
                mma_tf32(acc[1][nt], a[1], b0, b1, acc[1][nt]);
            }
        }
    }

    // Epilogue: residual add + store (row = channel, cols = tokens).
#pragma unroll
    for (int mt = 0; mt < 2; mt++)
#pragma unroll
        for (int nt = 0; nt < 8; nt++) {
            size_t r0 = ((size_t)b * CIN + c0 + wm * 32 + mt * 16 + gp) * NTOK
                        + n0 + wn * 64 + nt * 8 + 2 * tg;
            size_t r1 = r0 + (size_t)8 * NTOK;
            float2 x0 = *(const float2*)(x + r0);
            float2 x1 = *(const float2*)(x + r1);
            *(float2*)(out + r0) = make_float2(x0.x + acc[mt][nt][0],
                                               x0.y + acc[mt][nt][1]);
            *(float2*)(out + r1) = make_float2(x1.x + acc[mt][nt][2],
                                               x1.y + acc[mt][nt][3]);
        }
}

// ---------------------------------------------------------------------------
extern "C" void kernel_launch(void* const* d_in, const int* in_sizes, int n_in,
                              void* d_out, int out_size) {
    const float* x = nullptr; const float* w_in = nullptr; const float* w_out = nullptr;
    for (int i = 0; i < n_in; i++) {
        if (in_sizes[i] == BATCH * CIN * NTOK)      x     = (const float*)d_in[i];
        else if (in_sizes[i] == 3 * CRD * CIN)      w_in  = (const float*)d_in[i];
        else if (in_sizes[i] == CIN * CRD)          w_out = (const float*)d_in[i];
    }

    const int attn_smem = (64 * KS_STRIDE + 64 * GS_STRIDE + 8 * 16 * PS_STRIDE)
                          * (int)sizeof(float);   // 103,424 B

    static int attr_done = 0;
    if (!attr_done) {
        cudaFuncSetAttribute(attn_tc_kernel,
                             cudaFuncAttributeMaxDynamicSharedMemorySize, attn_smem);
        cudaFuncSetAttribute(attn_tc_kernel,
                             cudaFuncAttributePreferredSharedMemoryCarveout, 100);
        attr_done = 1;
    }

    proj_tc_kernel<<<dim3(32, 3, 8), 256>>>(x, w_in);
    attn_tc_kernel<<<dim3(32, 8), 256, attn_smem>>>();
    out_tc_kernel<<<dim3(32, 4, 8), 256>>>(x, w_out, (float*)d_out);
}